// round 7
// baseline (speedup 1.0000x reference)
#include <cuda_runtime.h>
#include <math_constants.h>

// Shapes: img (B=2, C=1, D=192, H=192, W=192) float32.
static constexpr int B   = 2;
static constexpr int DD  = 192;
static constexpr int HH  = 192;
static constexpr int WW  = 192;
static constexpr int PLANE = HH * WW;        // 36864
static constexpr int VOL   = DD * PLANE;     // 7077888
static constexpr int NTOT  = B * VOL;        // 14155776

static constexpr int TX   = 32;              // tile x
static constexpr int TY   = 32;              // tile y (2 rows per thread)
static constexpr int TYB  = 16;              // block y threads
static constexpr int NTHR = TX * TYB;        // 512
static constexpr int ZCHUNK = 24;
static constexpr int NCH    = DD / ZCHUNK;   // 8

// Ping-pong erosion buffers (scratch: __device__ globals, no allocation).
__device__ float g_buf0[NTOT];
__device__ float g_buf1[NTOT];

// One fused soft-skeletonize step:
//   Eout = soft_erode(A)                 (7-pt cross min, +inf pad)
//   d    = dilate3x3x3(Eout)             (-inf pad)
//   delta = relu(A - d)
//   skel  = first ? delta : skel + relu(delta - skel*delta)
__global__ __launch_bounds__(NTHR, 4)
void fused_step(const float* __restrict__ A,
                float* __restrict__ Eout,
                float* __restrict__ skel,
                int first)
{
    // A ring: 4 planes of the input with halo 2 in x,y.
    __shared__ float As[4][TY + 4][TX + 4];      // 20736 B
    // Erode plane scratch (halo 1), rebuilt each iteration.
    __shared__ float eb[TY + 2][TX + 2];         //  4624 B
    // Row-max ring: rxs[j%4][y][x] = max3x(e(j)), halo 1 in y.
    __shared__ float rxs[4][TY + 2][TX];         // 17408 B

    const int tx  = threadIdx.x;
    const int ty  = threadIdx.y;                 // 0..15
    const int tid = ty * TX + tx;
    const int x0  = blockIdx.x * TX;
    const int y0  = blockIdx.y * TY;
    const int bz  = blockIdx.z;
    const int b   = bz >> 3;                     // NCH == 8
    const int z0  = (bz & 7) * ZCHUNK;
    const int z1  = z0 + ZCHUNK;

    const float* __restrict__ Ab = A    + b * VOL;
    float* __restrict__ Eb       = Eout + b * VOL;
    float* __restrict__ Sb       = skel + b * VOL;

    const float PINF = CUDART_INF_F;
    const float NINF = -CUDART_INF_F;

    float acap[2];   // A(z) tile-center values, captured one iter ahead

    // Load input plane j into A-ring slot (j&3). z-OOB -> +inf plane;
    // xy-OOB positions -> +inf (erode min-padding).
    auto loadA = [&](int j) {
        float* s = &As[(j + 8) & 3][0][0];
        constexpr int NA = (TY + 4) * (TX + 4);   // 1296
        if ((unsigned)j < (unsigned)DD) {
            const float* src = Ab + j * PLANE;
            #pragma unroll
            for (int i = tid; i < NA; i += NTHR) {
                int yy = i / (TX + 4);
                int xx = i - yy * (TX + 4);
                int gy = y0 + yy - 2;
                int gx = x0 + xx - 2;
                float v = PINF;
                if ((unsigned)gy < (unsigned)HH && (unsigned)gx < (unsigned)WW)
                    v = __ldg(src + gy * WW + gx);
                s[i] = v;
            }
        } else {
            #pragma unroll
            for (int i = tid; i < NA; i += NTHR) s[i] = PINF;
        }
    };

    // Compute erode plane j into eb (halo 1). Invalid -> -inf so the
    // downstream dilate-max ignores it.
    auto compute_e = [&](int j) {
        const int sj  = (j + 8) & 3;
        const int sjm = (j + 7) & 3;
        const int sjp = (j + 9) & 3;
        const bool jv = (unsigned)j < (unsigned)DD;
        constexpr int NE = (TY + 2) * (TX + 2);   // 1156
        #pragma unroll
        for (int i = tid; i < NE; i += NTHR) {
            int yy = i / (TX + 2);
            int xx = i - yy * (TX + 2);
            int gy = y0 + yy - 1;
            int gx = x0 + xx - 1;
            float r = NINF;
            if (jv && (unsigned)gy < (unsigned)HH && (unsigned)gx < (unsigned)WW) {
                float m = As[sj][yy + 1][xx + 1];
                m = fminf(m, As[sjm][yy + 1][xx + 1]);
                m = fminf(m, As[sjp][yy + 1][xx + 1]);
                m = fminf(m, As[sj][yy    ][xx + 1]);
                m = fminf(m, As[sj][yy + 2][xx + 1]);
                m = fminf(m, As[sj][yy + 1][xx    ]);
                m = fminf(m, As[sj][yy + 1][xx + 2]);
                r = m;
            }
            eb[yy][xx] = r;
        }
    };

    // rx(j) = max3x(e(j)) into rx-ring slot ((j+4)%4); optionally store the
    // interior of e(j) to gmem (each plane written by exactly one chunk).
    auto compute_rx_store = [&](int j, bool do_store) {
        const int sr = (j + 4) & 3;               // j >= -1
        constexpr int NR = (TY + 2) * TX;         // 1088
        #pragma unroll
        for (int i = tid; i < NR; i += NTHR) {
            int yy = i >> 5;                       // TX == 32
            int x  = i & 31;
            float m = fmaxf(fmaxf(eb[yy][x], eb[yy][x + 1]), eb[yy][x + 2]);
            rxs[sr][yy][x] = m;
        }
        if (do_store) {
            float* dst = Eb + j * PLANE + (y0 + ty) * WW + (x0 + tx);
            dst[0]        = eb[ty + 1][tx + 1];
            dst[TYB * WW] = eb[ty + TYB + 1][tx + 1];
        }
    };

    auto capture = [&](int z) {
        const int sa = (z + 8) & 3;
        acap[0] = As[sa][ty + 2][tx + 2];
        acap[1] = As[sa][ty + TYB + 2][tx + 2];
    };

    // Output at plane z: dilate from rx ring, delta, skel update. 2 rows.
    // Uses acap (A(z) centers captured earlier).
    auto do_output = [&](int z) {
        const int s0 = (z + 3) & 3;  // rx(z-1)
        const int s1 = (z + 4) & 3;  // rx(z)
        const int s2 = (z + 5) & 3;  // rx(z+1)
        #pragma unroll
        for (int h = 0; h < 2; h++) {
            const int yy = ty + h * TYB;
            float m = NINF;
            #pragma unroll
            for (int dy = 0; dy < 3; dy++) {
                m = fmaxf(m, rxs[s0][yy + dy][tx]);
                m = fmaxf(m, rxs[s1][yy + dy][tx]);
                m = fmaxf(m, rxs[s2][yy + dy][tx]);
            }
            float delta = fmaxf(acap[h] - m, 0.0f);
            int g = z * PLANE + (y0 + yy) * WW + (x0 + tx);
            if (first) {
                Sb[g] = delta;
            } else {
                float s = Sb[g];
                Sb[g] = s + fmaxf(delta - s * delta, 0.0f);
            }
        }
    };

    // --- prologue: prime As(z0-2..z0+3), rx(z0-1..z0+1), store e(z0,z0+1),
    //     capture a(z0).
    loadA(z0 - 2);
    loadA(z0 - 1);
    loadA(z0);
    loadA(z0 + 1);
    __syncthreads();

    compute_e(z0 - 1);
    __syncthreads();
    compute_rx_store(z0 - 1, false);
    __syncthreads();

    compute_e(z0);
    loadA(z0 + 2);               // overwrites As(z0-2), dead after e(z0-1)
    __syncthreads();
    compute_rx_store(z0, true);
    __syncthreads();

    compute_e(z0 + 1);
    loadA(z0 + 3);               // overwrites As(z0-1), dead after e(z0)
    __syncthreads();
    compute_rx_store(z0 + 1, true);
    capture(z0);
    __syncthreads();

    // --- main loop: iteration z emits output z-1, computes rx(z+1). 2 syncs.
    for (int z = z0 + 1; z < z1; z++) {
        compute_e(z + 1);        // reads As(z..z+2)
        loadA(z + 3);            // writes slot (z+3)&3 == old As(z-1)
        __syncthreads();
        compute_rx_store(z + 1, (z + 1) < z1);
        do_output(z - 1);        // reads rx(z-2..z), acap = A(z-1)
        capture(z);              // A(z) center before its slot is recycled
        __syncthreads();
    }

    // --- epilogue: last output plane
    do_output(z1 - 1);           // reads rx(z1-2..z1), acap = A(z1-1)
}

extern "C" void kernel_launch(void* const* d_in, const int* in_sizes, int n_in,
                              void* d_out, int out_size) {
    const float* img = (const float*)d_in[0];
    float* skel = (float*)d_out;

    float *b0 = nullptr, *b1 = nullptr;
    cudaGetSymbolAddress((void**)&b0, g_buf0);
    cudaGetSymbolAddress((void**)&b1, g_buf1);

    dim3 grid(WW / TX, HH / TY, NCH * B);   // 6 x 6 x 16 = 576 blocks
    dim3 blk(TX, TYB, 1);                   // 512 threads

    const float* src = img;
    for (int k = 0; k <= 40; k++) {         // 41 fused steps: E_k -> E_{k+1}
        float* dst = (k & 1) ? b1 : b0;
        fused_step<<<grid, blk>>>(src, dst, skel, k == 0 ? 1 : 0);
        src = dst;
    }
}

// round 8
// speedup vs baseline: 1.3306x; 1.3306x over previous
#include <cuda_runtime.h>
#include <math_constants.h>

// Shapes: img (B=2, C=1, D=192, H=192, W=192) float32.
static constexpr int B   = 2;
static constexpr int DD  = 192;
static constexpr int HH  = 192;
static constexpr int WW  = 192;
static constexpr int PLANE = HH * WW;        // 36864
static constexpr int VOL   = DD * PLANE;     // 7077888
static constexpr int NTOT  = B * VOL;        // 14155776

static constexpr int TX   = 32;              // tile x
static constexpr int TY   = 32;              // tile y (2 rows per thread)
static constexpr int TYB  = 16;              // block y threads
static constexpr int NTHR = TX * TYB;        // 512
static constexpr int ZCHUNK = 24;
static constexpr int NCH    = DD / ZCHUNK;   // 8

static constexpr int AW  = 36;               // As plane width  (halo 2)
static constexpr int APL = AW * AW;          // 1296 words / plane
static constexpr int EW  = 34;               // eb width (halo 1)
static constexpr int RW  = 32;               // rxs width
static constexpr int RPL = 34 * RW;          // 1088 words / plane

// Ping-pong erosion buffers (scratch: __device__ globals, no allocation).
__device__ float g_buf0[NTOT];
__device__ float g_buf1[NTOT];

// One fused soft-skeletonize step:
//   Eout = soft_erode(A)                 (7-pt cross min, +inf pad)
//   d    = dilate3x3x3(Eout)             (-inf pad)
//   delta = relu(A - d)
//   skel  = FIRST ? delta : skel + relu(delta - skel*delta)
template <int FIRST>
__global__ __launch_bounds__(NTHR, 3)
void fused_step(const float* __restrict__ A,
                float* __restrict__ Eout,
                float* __restrict__ skel)
{
    __shared__ float As[4 * APL];   // input ring, 4 planes, halo 2
    __shared__ float eb[EW * EW];   // erode plane, halo 1
    __shared__ float rxs[4 * RPL];  // row-max ring (slot = plane mod 4)

    const int tx  = threadIdx.x;
    const int ty  = threadIdx.y;                 // 0..15
    const int tid = ty * TX + tx;
    const int x0  = blockIdx.x * TX;
    const int y0  = blockIdx.y * TY;
    const int bz  = blockIdx.z;
    const int b   = bz >> 3;                     // NCH == 8
    const int z0  = (bz & 7) * ZCHUNK;           // z0 % 4 == 0
    const int z1  = z0 + ZCHUNK;

    const float* __restrict__ Ab = A    + b * VOL;
    float* __restrict__ EbB      = Eout + b * VOL;
    float* __restrict__ SbB      = skel + b * VOL;

    const float PINF = CUDART_INF_F;
    const float NINF = -CUDART_INF_F;

    // ================= z-invariant per-thread precomputation ==============

    // loadA: 1296 elements = 512 + 512 + 272
    int  ga0, ga1, ga2;
    bool av0, av1, av2;
    const bool act2 = (tid + 2 * NTHR) < APL;    // tid < 272
    {
        int i, yy, xx, gy, gx;
        i = tid;            yy = i / AW; xx = i - yy * AW;
        gy = y0 + yy - 2;   gx = x0 + xx - 2;
        av0 = ((unsigned)gy < (unsigned)HH) && ((unsigned)gx < (unsigned)WW);
        ga0 = av0 ? gy * WW + gx : 0;
        i = tid + NTHR;     yy = i / AW; xx = i - yy * AW;
        gy = y0 + yy - 2;   gx = x0 + xx - 2;
        av1 = ((unsigned)gy < (unsigned)HH) && ((unsigned)gx < (unsigned)WW);
        ga1 = av1 ? gy * WW + gx : 0;
        i = tid + 2 * NTHR; yy = i / AW; xx = i - yy * AW;
        gy = y0 + yy - 2;   gx = x0 + xx - 2;
        av2 = act2 && ((unsigned)gy < (unsigned)HH) && ((unsigned)gx < (unsigned)WW);
        ga2 = av2 ? gy * WW + gx : 0;
    }

    // erode positions: interior (ty,tx)+(ty+16,tx) plus L-shaped halo.
    const int  aoffA = (ty + 1) * AW + (tx + 1);
    const int  eoffA = ty * EW + tx;
    const bool evA0 = ((unsigned)(y0 + ty - 1)  < (unsigned)HH) &&
                      ((unsigned)(x0 + tx - 1)  < (unsigned)WW);
    const bool evA1 = ((unsigned)(y0 + ty + 15) < (unsigned)HH) &&
                      ((unsigned)(x0 + tx - 1)  < (unsigned)WW);
    // halo: tid<68 -> cols 32,33 (rows 0..33); 68<=tid<132 -> rows 32,33 (cols 0..31)
    const bool act2e = tid < 132;
    int r2, c2;
    if (tid < 68) { r2 = tid >> 1;              c2 = 32 + (tid & 1); }
    else          { int t = tid - 68; r2 = 32 + (t >> 5); c2 = t & 31; }
    const int  aoff2 = (r2 + 1) * AW + (c2 + 1);
    const int  eoff2 = r2 * EW + c2;
    const bool ev2 = act2e && ((unsigned)(y0 + r2 - 1) < (unsigned)HH) &&
                              ((unsigned)(x0 + c2 - 1) < (unsigned)WW);

    // rx positions: interior 2 rows + bottom-halo rows 32,33 (tid<64)
    const int  routA = ty * RW + tx;
    const bool actR2 = tid < 64;
    const int  rR2 = 32 + (tid >> 5), cR2 = tid & 31;
    const int  rin2  = rR2 * EW + cR2;
    const int  rout2 = rR2 * RW + cR2;

    // gmem / center offsets
    const int rowg = (y0 + ty) * WW + (x0 + tx);      // +16*WW for h=1
    const int ecen = (ty + 1) * EW + (tx + 1);        // +16*EW
    const int acen = (ty + 2) * AW + (tx + 2);        // +16*AW

    float acap0, acap1;

    // ========================= helpers ====================================

    auto loadAfn = [&](const float* src, bool zv, int slot) {
        float* s = As + slot * APL;
        float v0 = (zv && av0) ? __ldg(src + ga0) : PINF;
        float v1 = (zv && av1) ? __ldg(src + ga1) : PINF;
        s[tid]        = v0;
        s[tid + NTHR] = v1;
        if (act2) {
            float v2 = (zv && av2) ? __ldg(src + ga2) : PINF;
            s[tid + 2 * NTHR] = v2;
        }
    };

    auto e7 = [&](int sC, int sM, int sP, int aoff) {
        const float* c = As + sC * APL;
        float m = fminf(c[aoff], fminf(As[sM * APL + aoff], As[sP * APL + aoff]));
        m = fminf(m, fminf(c[aoff - AW], c[aoff + AW]));
        m = fminf(m, fminf(c[aoff - 1],  c[aoff + 1]));
        return m;
    };

    auto compute_e = [&](int sC, int sM, int sP, bool jv) {
        float m0 = e7(sC, sM, sP, aoffA);
        float m1 = e7(sC, sM, sP, aoffA + 16 * AW);
        eb[eoffA]           = (jv && evA0) ? m0 : NINF;
        eb[eoffA + 16 * EW] = (jv && evA1) ? m1 : NINF;
        if (act2e) {
            float m2 = e7(sC, sM, sP, aoff2);
            eb[eoff2] = (jv && ev2) ? m2 : NINF;
        }
    };

    auto compute_rx = [&](int slot, bool store, float* pE) {
        float* r = rxs + slot * RPL;
        int i0 = eoffA;
        r[routA] = fmaxf(fmaxf(eb[i0], eb[i0 + 1]), eb[i0 + 2]);
        int i1 = eoffA + 16 * EW;
        r[routA + 16 * RW] = fmaxf(fmaxf(eb[i1], eb[i1 + 1]), eb[i1 + 2]);
        if (actR2)
            r[rout2] = fmaxf(fmaxf(eb[rin2], eb[rin2 + 1]), eb[rin2 + 2]);
        if (store) {
            pE[rowg]           = eb[ecen];
            pE[rowg + 16 * WW] = eb[ecen + 16 * EW];
        }
    };

    auto capture = [&](int slot) {
        acap0 = As[slot * APL + acen];
        acap1 = As[slot * APL + acen + 16 * AW];
    };

    auto do_output = [&](int s0, int s1, int s2, float* pS) {
        #pragma unroll
        for (int h = 0; h < 2; h++) {
            const int base = routA + h * 16 * RW;
            float m = rxs[s0 * RPL + base];
            m = fmaxf(m, rxs[s0 * RPL + base + RW]);
            m = fmaxf(m, rxs[s0 * RPL + base + 2 * RW]);
            m = fmaxf(m, rxs[s1 * RPL + base]);
            m = fmaxf(m, rxs[s1 * RPL + base + RW]);
            m = fmaxf(m, rxs[s1 * RPL + base + 2 * RW]);
            m = fmaxf(m, rxs[s2 * RPL + base]);
            m = fmaxf(m, rxs[s2 * RPL + base + RW]);
            m = fmaxf(m, rxs[s2 * RPL + base + 2 * RW]);
            float a = h ? acap1 : acap0;
            float delta = fmaxf(a - m, 0.0f);
            int g = rowg + h * 16 * WW;
            if (FIRST) {
                pS[g] = delta;
            } else {
                float s = pS[g];
                pS[g] = s + fmaxf(delta - s * delta, 0.0f);
            }
        }
    };

    // ===================== prologue (slots compile-time) ===================
    // slot(j) = j mod 4; z0 % 4 == 0.
    loadAfn(Ab + (z0 - 2) * PLANE, z0 - 2 >= 0, 2);
    loadAfn(Ab + (z0 - 1) * PLANE, z0 - 1 >= 0, 3);
    loadAfn(Ab + (z0    ) * PLANE, true,        0);
    loadAfn(Ab + (z0 + 1) * PLANE, true,        1);
    __syncthreads();

    compute_e(3, 2, 0, z0 - 1 >= 0);           // e(z0-1)
    __syncthreads();
    compute_rx(3, false, EbB);
    __syncthreads();

    compute_e(0, 3, 1, true);                  // e(z0)
    loadAfn(Ab + (z0 + 2) * PLANE, true, 2);
    __syncthreads();
    compute_rx(0, true, EbB + z0 * PLANE);
    __syncthreads();

    compute_e(1, 0, 2, true);                  // e(z0+1)
    loadAfn(Ab + (z0 + 3) * PLANE, true, 3);
    __syncthreads();
    compute_rx(1, true, EbB + (z0 + 1) * PLANE);
    capture(0);                                // A(z0)
    __syncthreads();

    // ===================== main loop: 23 bodies, 4-phase ===================
    const float* pA = Ab  + (z0 + 4) * PLANE;  // loadA target plane z+3
    float* pE       = EbB + (z0 + 2) * PLANE;  // e-store plane z+1
    float* pS       = SbB + (z0    ) * PLANE;  // output plane z-1

    // body(z): compute_e(z+1), loadA(z+3) | compute_rx(z+1), out(z-1), cap(z)
    auto body = [&](int z, int eC, int eM, int eP, int L, int rxW,
                    int rO0, int rO1, int rO2, int cap) {
        compute_e(eC, eM, eP, (z + 1) < DD);
        loadAfn(pA, (z + 3) < DD, L);
        __syncthreads();
        compute_rx(rxW, (z + 1) < z1, pE);
        do_output(rO0, rO1, rO2, pS);
        capture(cap);
        __syncthreads();
        pA += PLANE; pE += PLANE; pS += PLANE;
    };

    int z = z0 + 1;                            // z % 4 == 1
    #pragma unroll 1
    for (int m = 0; m < 5; m++) {
        body(z, 2, 1, 3, 0, 2, 3, 0, 1, 1); z++;   // phase 1
        body(z, 3, 2, 0, 1, 3, 0, 1, 2, 2); z++;   // phase 2
        body(z, 0, 3, 1, 2, 0, 1, 2, 3, 3); z++;   // phase 3
        body(z, 1, 0, 2, 3, 1, 2, 3, 0, 0); z++;   // phase 0
    }
    body(z, 2, 1, 3, 0, 2, 3, 0, 1, 1); z++;       // z0+21
    body(z, 3, 2, 0, 1, 3, 0, 1, 2, 2); z++;       // z0+22
    body(z, 0, 3, 1, 2, 0, 1, 2, 3, 3); z++;       // z0+23

    // epilogue: output plane z1-1 (z1-1 % 4 == 3); reads rx(z1-2..z1)
    do_output(2, 3, 0, pS);
}

extern "C" void kernel_launch(void* const* d_in, const int* in_sizes, int n_in,
                              void* d_out, int out_size) {
    const float* img = (const float*)d_in[0];
    float* skel = (float*)d_out;

    float *b0 = nullptr, *b1 = nullptr;
    cudaGetSymbolAddress((void**)&b0, g_buf0);
    cudaGetSymbolAddress((void**)&b1, g_buf1);

    dim3 grid(WW / TX, HH / TY, NCH * B);   // 6 x 6 x 16 = 576 blocks
    dim3 blk(TX, TYB, 1);                   // 512 threads

    fused_step<1><<<grid, blk>>>(img, b0, skel);
    const float* src = b0;
    for (int k = 1; k <= 40; k++) {
        float* dst = (k & 1) ? b1 : b0;
        fused_step<0><<<grid, blk>>>(src, dst, skel);
        src = dst;
    }
}

// round 9
// speedup vs baseline: 1.6042x; 1.2056x over previous
#include <cuda_runtime.h>
#include <math_constants.h>

// Shapes: img (B=2, C=1, D=192, H=192, W=192) float32.
static constexpr int B   = 2;
static constexpr int DD  = 192;
static constexpr int HH  = 192;
static constexpr int WW  = 192;
static constexpr int PLANE = HH * WW;        // 36864
static constexpr int VOL   = DD * PLANE;     // 7077888
static constexpr int NTOT  = B * VOL;        // 14155776

static constexpr int TX   = 32;              // tile x
static constexpr int TYB  = 16;              // block y threads (tile y = 32)
static constexpr int NTHR = TX * TYB;        // 512
static constexpr int ZCHUNK = 48;            // z0 % 6 == 0 for all chunks
static constexpr int NCH    = DD / ZCHUNK;   // 4

static constexpr int AW  = 36;               // As plane width  (halo 2)
static constexpr int APL = AW * AW;          // 1296
static constexpr int EW  = 34;               // eb width (halo 1)
static constexpr int EPL = EW * EW;          // 1156
static constexpr int RW  = 32;               // rxs width
static constexpr int RPL = 34 * RW;          // 1088

static constexpr int SM_FLOATS = 6 * APL + 6 * RPL + 2 * EPL;  // 16616
static constexpr int SM_BYTES  = SM_FLOATS * 4;                // 66464

// Ping-pong erosion buffers (scratch: __device__ globals, no allocation).
__device__ float g_buf0[NTOT];
__device__ float g_buf1[NTOT];

// One fused soft-skeletonize step:
//   Eout = soft_erode(A)                 (7-pt cross min, +inf pad)
//   d    = dilate3x3x3(Eout)             (-inf pad)
//   delta = relu(A - d)
//   skel  = FIRST ? delta : skel + relu(delta - skel*delta)
//
// 2 z-planes per pipeline iteration, 1 __syncthreads per plane.
template <int FIRST>
__global__ __launch_bounds__(NTHR, 2)
void fused_step(const float* __restrict__ A,
                float* __restrict__ Eout,
                float* __restrict__ skel)
{
    extern __shared__ float sm[];
    float* As  = sm;                         // 6 planes, halo 2, slot = j%6
    float* rxs = sm + 6 * APL;               // 6 planes row-max, slot = j%6
    float* eb  = sm + 6 * APL + 6 * RPL;     // 2 erode planes (halo 1)

    const int tx  = threadIdx.x;
    const int ty  = threadIdx.y;             // 0..15
    const int tid = ty * TX + tx;
    const int x0  = blockIdx.x * TX;
    const int y0  = blockIdx.y * 32;
    const int bz  = blockIdx.z;
    const int b   = bz >> 2;                 // NCH == 4
    const int z0  = (bz & 3) * ZCHUNK;       // z0 % 6 == 0
    const int z1  = z0 + ZCHUNK;

    const float* __restrict__ Ab = A    + b * VOL;
    float* __restrict__ EbB      = Eout + b * VOL;
    float* __restrict__ SbB      = skel + b * VOL;

    const float PINF = CUDART_INF_F;
    const float NINF = -CUDART_INF_F;

    // ================= z-invariant per-thread precomputation ==============

    // loadA: 1296 elements = 512 + 512 + 272
    int  ga0, ga1, ga2;
    bool av0, av1, av2;
    const bool act2 = (tid + 2 * NTHR) < APL;    // tid < 272
    {
        int i, yy, xx, gy, gx;
        i = tid;            yy = i / AW; xx = i - yy * AW;
        gy = y0 + yy - 2;   gx = x0 + xx - 2;
        av0 = ((unsigned)gy < (unsigned)HH) && ((unsigned)gx < (unsigned)WW);
        ga0 = av0 ? gy * WW + gx : 0;
        i = tid + NTHR;     yy = i / AW; xx = i - yy * AW;
        gy = y0 + yy - 2;   gx = x0 + xx - 2;
        av1 = ((unsigned)gy < (unsigned)HH) && ((unsigned)gx < (unsigned)WW);
        ga1 = av1 ? gy * WW + gx : 0;
        i = tid + 2 * NTHR; yy = i / AW; xx = i - yy * AW;
        gy = y0 + yy - 2;   gx = x0 + xx - 2;
        av2 = act2 && ((unsigned)gy < (unsigned)HH) && ((unsigned)gx < (unsigned)WW);
        ga2 = av2 ? gy * WW + gx : 0;
    }

    // erode positions: interior (ty,tx)+(ty+16,tx) plus L-shaped halo.
    const int  aoffA = (ty + 1) * AW + (tx + 1);
    const int  eoffA = ty * EW + tx;
    const bool evA0 = ((unsigned)(y0 + ty - 1)  < (unsigned)HH) &&
                      ((unsigned)(x0 + tx - 1)  < (unsigned)WW);
    const bool evA1 = ((unsigned)(y0 + ty + 15) < (unsigned)HH) &&
                      ((unsigned)(x0 + tx - 1)  < (unsigned)WW);
    // halo: tid<68 -> cols 32,33 (rows 0..33); 68<=tid<132 -> rows 32,33
    const bool act2e = tid < 132;
    int r2, c2;
    if (tid < 68) { r2 = tid >> 1;              c2 = 32 + (tid & 1); }
    else          { int t = tid - 68; r2 = 32 + (t >> 5); c2 = t & 31; }
    const int  aoff2 = (r2 + 1) * AW + (c2 + 1);
    const int  eoff2 = r2 * EW + c2;
    const bool ev2 = act2e && ((unsigned)(y0 + r2 - 1) < (unsigned)HH) &&
                              ((unsigned)(x0 + c2 - 1) < (unsigned)WW);

    // rx positions: interior 2 rows + bottom-halo rows 32,33 (tid<64)
    const int  routA = ty * RW + tx;
    const bool actR2 = tid < 64;
    const int  rR2 = 32 + (tid >> 5), cR2 = tid & 31;
    const int  rin2  = rR2 * EW + cR2;
    const int  rout2 = rR2 * RW + cR2;

    // gmem / center offsets
    const int rowg = (y0 + ty) * WW + (x0 + tx);      // +16*WW for h=1
    const int ecen = (ty + 1) * EW + (tx + 1);        // +16*EW
    const int acen = (ty + 2) * AW + (tx + 2);        // +16*AW

    float cA0, cA1, cB0, cB1;   // captured A centers (planes w-2, w-1)

    // ========================= helpers ====================================

    auto loadAfn = [&](const float* src, bool zv, int slot) {
        float* s = As + slot * APL;
        float v0 = (zv && av0) ? __ldg(src + ga0) : PINF;
        float v1 = (zv && av1) ? __ldg(src + ga1) : PINF;
        s[tid]        = v0;
        s[tid + NTHR] = v1;
        if (act2) {
            float v2 = (zv && av2) ? __ldg(src + ga2) : PINF;
            s[tid + 2 * NTHR] = v2;
        }
    };

    auto e7 = [&](int sC, int sM, int sP, int aoff) {
        const float* c = As + sC * APL;
        float m = fminf(c[aoff], fminf(As[sM * APL + aoff], As[sP * APL + aoff]));
        m = fminf(m, fminf(c[aoff - AW], c[aoff + AW]));
        m = fminf(m, fminf(c[aoff - 1],  c[aoff + 1]));
        return m;
    };

    auto compute_e = [&](int ep, int sC, int sM, int sP, bool jv) {
        float* e = eb + ep * EPL;
        float m0 = e7(sC, sM, sP, aoffA);
        float m1 = e7(sC, sM, sP, aoffA + 16 * AW);
        e[eoffA]           = (jv && evA0) ? m0 : NINF;
        e[eoffA + 16 * EW] = (jv && evA1) ? m1 : NINF;
        if (act2e) {
            float m2 = e7(sC, sM, sP, aoff2);
            e[eoff2] = (jv && ev2) ? m2 : NINF;
        }
    };

    auto compute_rx = [&](int ep, int slot, bool store, float* pEo) {
        const float* e = eb + ep * EPL;
        float* r = rxs + slot * RPL;
        int i0 = eoffA;
        r[routA] = fmaxf(fmaxf(e[i0], e[i0 + 1]), e[i0 + 2]);
        int i1 = eoffA + 16 * EW;
        r[routA + 16 * RW] = fmaxf(fmaxf(e[i1], e[i1 + 1]), e[i1 + 2]);
        if (actR2)
            r[rout2] = fmaxf(fmaxf(e[rin2], e[rin2 + 1]), e[rin2 + 2]);
        if (store) {
            pEo[rowg]           = e[ecen];
            pEo[rowg + 16 * WW] = e[ecen + 16 * EW];
        }
    };

    auto do_output = [&](int s0, int s1, int s2, float* pSo,
                         float a0, float a1) {
        #pragma unroll
        for (int h = 0; h < 2; h++) {
            const int base = routA + h * 16 * RW;
            float m = rxs[s0 * RPL + base];
            m = fmaxf(m, rxs[s0 * RPL + base + RW]);
            m = fmaxf(m, rxs[s0 * RPL + base + 2 * RW]);
            m = fmaxf(m, rxs[s1 * RPL + base]);
            m = fmaxf(m, rxs[s1 * RPL + base + RW]);
            m = fmaxf(m, rxs[s1 * RPL + base + 2 * RW]);
            m = fmaxf(m, rxs[s2 * RPL + base]);
            m = fmaxf(m, rxs[s2 * RPL + base + RW]);
            m = fmaxf(m, rxs[s2 * RPL + base + 2 * RW]);
            float a = h ? a1 : a0;
            float delta = fmaxf(a - m, 0.0f);
            int g = rowg + h * 16 * WW;
            if (FIRST) {
                pSo[g] = delta;
            } else {
                float s = pSo[g];
                pSo[g] = s + fmaxf(delta - s * delta, 0.0f);
            }
        }
    };

    // ===================== prologue (slot(j) = j mod 6, z0%6==0) ===========
    loadAfn(Ab + (z0 - 2) * PLANE, z0 - 2 >= 0, 4);
    loadAfn(Ab + (z0 - 1) * PLANE, z0 - 1 >= 0, 5);
    loadAfn(Ab + (z0    ) * PLANE, true, 0);
    loadAfn(Ab + (z0 + 1) * PLANE, true, 1);
    loadAfn(Ab + (z0 + 2) * PLANE, true, 2);
    loadAfn(Ab + (z0 + 3) * PLANE, true, 3);
    __syncthreads();

    compute_e(0, 5, 4, 0, z0 - 1 >= 0);       // e(z0-1)
    compute_e(1, 0, 5, 1, true);              // e(z0)
    __syncthreads();

    compute_rx(0, 5, false, EbB);             // rx(z0-1)
    compute_rx(1, 0, true,  EbB + z0 * PLANE);// rx(z0), store e(z0)
    cA0 = As[0 * APL + acen]; cA1 = As[0 * APL + acen + 16 * AW];  // A(z0)
    cB0 = As[1 * APL + acen]; cB1 = As[1 * APL + acen + 16 * AW];  // A(z0+1)
    __syncthreads();

    compute_e(0, 1, 0, 2, true);              // e(z0+1)
    compute_e(1, 2, 1, 3, true);              // e(z0+2)
    loadAfn(Ab + (z0 + 4) * PLANE, true, 4);  // over A(z0-2), dead
    loadAfn(Ab + (z0 + 5) * PLANE, true, 5);  // over A(z0-1), dead
    __syncthreads();

    compute_rx(0, 1, true, EbB + (z0 + 1) * PLANE);
    compute_rx(1, 2, true, EbB + (z0 + 2) * PLANE);
    __syncthreads();

    // ===================== main loop: 23 iterations, 2 planes each =========
    const float* pA = Ab  + (z0 + 6) * PLANE;  // loads planes w+4, w+5
    float* pE       = EbB + (z0 + 3) * PLANE;  // stores e(w+1), e(w+2)
    float* pS       = SbB + (z0    ) * PLANE;  // outputs w-2, w-1
    int w = z0 + 2;

    // body(w): A: e(w+1),e(w+2), load A(w+4),A(w+5) | B: rx, out(w-2),out(w-1)
    auto body = [&](int c1, int m1, int p1, int c2, int m2, int p2,
                    int L1, int L2, int r1, int r2s,
                    int a0, int a1, int a2, int b0s, int b1s, int b2s,
                    int cs0, int cs1)
    {
        compute_e(0, c1, m1, p1, (w + 1) < DD);
        compute_e(1, c2, m2, p2, (w + 2) < DD);
        loadAfn(pA,         (w + 4) < DD, L1);
        loadAfn(pA + PLANE, (w + 5) < DD, L2);
        __syncthreads();
        compute_rx(0, r1,  true,            pE);
        compute_rx(1, r2s, (w + 2) < z1,    pE + PLANE);
        do_output(a0,  a1,  a2,  pS,         cA0, cA1);
        do_output(b0s, b1s, b2s, pS + PLANE, cB0, cB1);
        cA0 = As[cs0 * APL + acen]; cA1 = As[cs0 * APL + acen + 16 * AW];
        cB0 = As[cs1 * APL + acen]; cB1 = As[cs1 * APL + acen + 16 * AW];
        __syncthreads();
        pA += 2 * PLANE; pE += 2 * PLANE; pS += 2 * PLANE;
        w += 2;
    };

    // phase w%6==2: e(w+1):C3,M2,P4  e(w+2):C4,M3,P5  L0,1  rx3,4
    //              out(w-2):(5,0,1) out(w-1):(0,1,2)  cap 2,3
    // phase w%6==4: e:C5,M4,P0 / C0,M5,P1  L2,3  rx5,0
    //              out:(1,2,3)/(2,3,4)  cap 4,5
    // phase w%6==0: e:C1,M0,P2 / C2,M1,P3  L4,5  rx1,2
    //              out:(3,4,5)/(4,5,0)  cap 0,1
    #pragma unroll 1
    for (int m = 0; m < 7; m++) {
        body(3,2,4, 4,3,5, 0,1, 3,4, 5,0,1, 0,1,2, 2,3);
        body(5,4,0, 0,5,1, 2,3, 5,0, 1,2,3, 2,3,4, 4,5);
        body(1,0,2, 2,1,3, 4,5, 1,2, 3,4,5, 4,5,0, 0,1);
    }
    body(3,2,4, 4,3,5, 0,1, 3,4, 5,0,1, 0,1,2, 2,3);   // w = z0+44
    body(5,4,0, 0,5,1, 2,3, 5,0, 1,2,3, 2,3,4, 4,5);   // w = z0+46

    // epilogue: outputs z0+46 (slots 3,4,5) and z0+47 (slots 4,5,0)
    do_output(3, 4, 5, pS,         cA0, cA1);
    do_output(4, 5, 0, pS + PLANE, cB0, cB1);
}

extern "C" void kernel_launch(void* const* d_in, const int* in_sizes, int n_in,
                              void* d_out, int out_size) {
    const float* img = (const float*)d_in[0];
    float* skel = (float*)d_out;

    float *b0 = nullptr, *b1 = nullptr;
    cudaGetSymbolAddress((void**)&b0, g_buf0);
    cudaGetSymbolAddress((void**)&b1, g_buf1);

    cudaFuncSetAttribute((const void*)fused_step<1>,
                         cudaFuncAttributeMaxDynamicSharedMemorySize, SM_BYTES);
    cudaFuncSetAttribute((const void*)fused_step<0>,
                         cudaFuncAttributeMaxDynamicSharedMemorySize, SM_BYTES);

    dim3 grid(WW / TX, HH / 32, NCH * B);   // 6 x 6 x 8 = 288 blocks
    dim3 blk(TX, TYB, 1);                   // 512 threads

    fused_step<1><<<grid, blk, SM_BYTES>>>(img, b0, skel);
    const float* src = b0;
    for (int k = 1; k <= 40; k++) {
        float* dst = (k & 1) ? b1 : b0;
        fused_step<0><<<grid, blk, SM_BYTES>>>(src, dst, skel);
        src = dst;
    }
}

// round 12
// speedup vs baseline: 1.6245x; 1.0126x over previous
#include <cuda_runtime.h>
#include <math_constants.h>

// Shapes: img (B=2, C=1, D=192, H=192, W=192) float32.
static constexpr int B   = 2;
static constexpr int DD  = 192;
static constexpr int HH  = 192;
static constexpr int WW  = 192;
static constexpr int PLANE = HH * WW;        // 36864
static constexpr int VOL   = DD * PLANE;     // 7077888
static constexpr int NTOT  = B * VOL;        // 14155776
static constexpr int WWW   = WW / 2;         // 96 gmem float2 words/row

static constexpr int NTHR = 512;
static constexpr int ZCHUNK = 48;            // z0 % 6 == 0
static constexpr int NCH    = DD / ZCHUNK;   // 4

// float2-word smem geometry
static constexpr int AWW = 18;               // A: 36 rows x 18 words (halo 2)
static constexpr int APW = 36 * AWW;         // 648
static constexpr int EWW = 18;               // e: 34 rows x 18 words (col c -> float idx c+1)
static constexpr int EPW = 34 * EWW;         // 612
static constexpr int RWW = 16;               // rx: 34 rows x 16 words
static constexpr int RPW = 34 * RWW;         // 544

static constexpr int SM_BYTES = (6 * APW + 6 * RPW + 2 * EPW) * 8;  // 67008

// Ping-pong erosion buffers (scratch: __device__ globals, no allocation).
__device__ float g_buf0[NTOT];
__device__ float g_buf1[NTOT];

// One fused soft-skeletonize step:
//   Eout = soft_erode(A)                 (7-pt cross min, +inf pad)
//   d    = dilate3x3x3(Eout)             (-inf pad)
//   delta = relu(A - d)
//   skel  = FIRST ? delta : skel + relu(delta - skel*delta)
// float2 datapath: each thread owns one x-pair; 2 planes per iteration,
// 1 __syncthreads per plane.
template <int FIRST>
__global__ __launch_bounds__(NTHR, 2)
void fused_step(const float* __restrict__ A,
                float* __restrict__ Eout,
                float* __restrict__ skel)
{
    extern __shared__ float2 sm2[];
    float2* As2 = sm2;                        // 6 planes, slot = j%6
    float2* rx2 = sm2 + 6 * APW;              // 6 planes, slot = j%6
    float2* eb2 = sm2 + 6 * APW + 6 * RPW;    // 2 scratch erode planes

    const int tid = threadIdx.x;
    const int x0  = blockIdx.x * 32;
    const int y0  = blockIdx.y * 32;
    const int bz  = blockIdx.z;
    const int bb  = bz >> 2;                  // NCH == 4
    const int z0  = (bz & 3) * ZCHUNK;        // z0 % 6 == 0
    const int z1  = z0 + ZCHUNK;

    const float* __restrict__ Ab = A    + bb * VOL;
    float* __restrict__ EbB      = Eout + bb * VOL;
    float* __restrict__ SbB      = skel + bb * VOL;

    const float PINF = CUDART_INF_F;
    const float NINF = -CUDART_INF_F;

    // ================= z-invariant per-thread precomputation ==============
    const int r = tid >> 4;                   // 0..31
    const int k = tid & 15;

    // e main pair: e row r, pair cols (2k+1, 2k+2); A word base row r+1
    const int  bA   = (r + 1) * AWW + k;
    const int  eStM = r * EWW + k + 1;
    const bool valE = ((unsigned)(y0 + r - 1) < (unsigned)HH);
    const bool stM  = (r >= 1);               // rows 1..31 store E
    const int  gEM  = (y0 + r - 1) * WWW + (x0 >> 1) + k;

    // e second pair (tid<32): rows 32,33
    const bool act2e = tid < 32;
    const int  r2    = 32 + (tid >> 4);
    const int  bA2   = (r2 + 1) * AWW + k;
    const int  eSt2  = r2 * EWW + k + 1;
    const bool valE2 = ((unsigned)(y0 + r2 - 1) < (unsigned)HH);
    const bool stM2  = (r2 == 32);
    const int  gEM2  = (y0 + r2 - 1) * WWW + (x0 >> 1) + k;

    // e edge scalars (tid in [64,132)): cols 0 and 33, rows 0..33
    const bool actEd = (tid >= 64) && (tid < 132);
    int aE = 0, eStE = 0; bool valEd = false;
    {
        int j   = tid - 64;
        int col = (j & 1) ? 33 : 0;
        int row = j >> 1;
        aE   = (row + 1) * 36 + (col + 1);    // A float idx
        eStE = row * 36 + (col + 1);          // e float idx
        int gx = x0 + col - 1;
        int gy = y0 + row - 1;
        valEd = actEd && ((unsigned)gx < (unsigned)WW) &&
                         ((unsigned)gy < (unsigned)HH);
    }

    // rx: main word tid (row r, pair k); second rows 32,33
    const int rbM = r * EWW + k;
    const int rb2 = r2 * EWW + k;

    // out / capture
    const int gw  = (y0 + r) * WWW + (x0 >> 1) + k;
    const int cAw = (r + 2) * AWW + k + 1;

    // loadA: 648 words = 512 + 136
    const bool actL1 = tid < (APW - NTHR);
    int la0g, la1g; bool la0v, la1v;
    {
        int row0 = tid / AWW, c0 = tid - row0 * AWW;
        int gy = y0 + row0 - 2, gx = x0 + 2 * c0 - 2;
        la0v = ((unsigned)gy < (unsigned)HH) && ((unsigned)gx < (unsigned)WW);
        la0g = la0v ? gy * WWW + (gx >> 1) : 0;
        int wi = tid + NTHR;
        int row1 = wi / AWW, c1 = wi - row1 * AWW;
        gy = y0 + row1 - 2; gx = x0 + 2 * c1 - 2;
        la1v = actL1 && ((unsigned)gy < (unsigned)HH) && ((unsigned)gx < (unsigned)WW);
        la1g = la1v ? gy * WWW + (gx >> 1) : 0;
    }

    float2 capA, capB;

    // ========================= helpers ====================================

    auto loadAfn = [&](const float* src, bool zv, int slot) {
        float2* s = As2 + slot * APW;
        const float2* g = (const float2*)src;
        float2 v0;
        if (zv && la0v) v0 = __ldg(g + la0g); else { v0.x = PINF; v0.y = PINF; }
        s[tid] = v0;
        if (actL1) {
            float2 v1;
            if (zv && la1v) v1 = __ldg(g + la1g); else { v1.x = PINF; v1.y = PINF; }
            s[tid + NTHR] = v1;
        }
    };

    auto compute_e = [&](int ep, int sC, int sM, int sP, bool jv,
                         bool st, float* pE) {
        float2* E = eb2 + ep * EPW;
        const float2* C = As2 + sC * APW;
        const float2* M = As2 + sM * APW;
        const float2* P = As2 + sP * APW;
        {   // main pair
            float2 w0 = C[bA], w1 = C[bA + 1], w2 = C[bA + 2];
            float2 up = C[bA + 1 - AWW], dn = C[bA + 1 + AWW];
            float2 zm = M[bA + 1], zp = P[bA + 1];
            float e0 = fminf(fminf(w1.x, fminf(up.x, dn.x)), fminf(zm.x, zp.x));
            e0 = fminf(e0, fminf(w0.y, w1.y));
            float e1 = fminf(fminf(w1.y, fminf(up.y, dn.y)), fminf(zm.y, zp.y));
            e1 = fminf(e1, fminf(w1.x, w2.x));
            bool v = jv && valE;
            float2 o; o.x = v ? e0 : NINF; o.y = v ? e1 : NINF;
            E[eStM] = o;
            if (st && stM) ((float2*)pE)[gEM] = o;
        }
        if (act2e) {  // rows 32,33
            float2 w0 = C[bA2], w1 = C[bA2 + 1], w2 = C[bA2 + 2];
            float2 up = C[bA2 + 1 - AWW], dn = C[bA2 + 1 + AWW];
            float2 zm = M[bA2 + 1], zp = P[bA2 + 1];
            float e0 = fminf(fminf(w1.x, fminf(up.x, dn.x)), fminf(zm.x, zp.x));
            e0 = fminf(e0, fminf(w0.y, w1.y));
            float e1 = fminf(fminf(w1.y, fminf(up.y, dn.y)), fminf(zm.y, zp.y));
            e1 = fminf(e1, fminf(w1.x, w2.x));
            bool v = jv && valE2;
            float2 o; o.x = v ? e0 : NINF; o.y = v ? e1 : NINF;
            E[eSt2] = o;
            if (st && stM2) ((float2*)pE)[gEM2] = o;
        }
        if (actEd) {  // scalar edge cols
            const float* Cf = (const float*)C;
            float m = fminf(Cf[aE], fminf(Cf[aE - 1], Cf[aE + 1]));
            m = fminf(m, fminf(Cf[aE - 36], Cf[aE + 36]));
            m = fminf(m, fminf(((const float*)M)[aE], ((const float*)P)[aE]));
            ((float*)E)[eStE] = (jv && valEd) ? m : NINF;
        }
    };

    auto compute_rx = [&](int ep, int slot) {
        const float2* E = eb2 + ep * EPW;
        float2* R = rx2 + slot * RPW;
        {
            float2 w0 = E[rbM], w1 = E[rbM + 1], w2 = E[rbM + 2];
            float2 o;
            float c = fmaxf(w1.x, w1.y);
            o.x = fmaxf(w0.y, c);
            o.y = fmaxf(w2.x, c);
            R[tid] = o;
        }
        if (act2e) {
            float2 w0 = E[rb2], w1 = E[rb2 + 1], w2 = E[rb2 + 2];
            float2 o;
            float c = fmaxf(w1.x, w1.y);
            o.x = fmaxf(w0.y, c);
            o.y = fmaxf(w2.x, c);
            R[NTHR + tid] = o;
        }
    };

    auto capture = [&](int slot) { return As2[slot * APW + cAw]; };

    auto do_output = [&](int s0, int s1, int s2, float* pS, float2 a) {
        const float2* R0 = rx2 + s0 * RPW;
        const float2* R1 = rx2 + s1 * RPW;
        const float2* R2 = rx2 + s2 * RPW;
        float2 m = R0[tid];
        float2 t;
        t = R0[tid + RWW];     m.x = fmaxf(m.x, t.x); m.y = fmaxf(m.y, t.y);
        t = R0[tid + 2*RWW];   m.x = fmaxf(m.x, t.x); m.y = fmaxf(m.y, t.y);
        t = R1[tid];           m.x = fmaxf(m.x, t.x); m.y = fmaxf(m.y, t.y);
        t = R1[tid + RWW];     m.x = fmaxf(m.x, t.x); m.y = fmaxf(m.y, t.y);
        t = R1[tid + 2*RWW];   m.x = fmaxf(m.x, t.x); m.y = fmaxf(m.y, t.y);
        t = R2[tid];           m.x = fmaxf(m.x, t.x); m.y = fmaxf(m.y, t.y);
        t = R2[tid + RWW];     m.x = fmaxf(m.x, t.x); m.y = fmaxf(m.y, t.y);
        t = R2[tid + 2*RWW];   m.x = fmaxf(m.x, t.x); m.y = fmaxf(m.y, t.y);
        float dx = fmaxf(a.x - m.x, 0.0f);
        float dy = fmaxf(a.y - m.y, 0.0f);
        float2* S = (float2*)pS;
        if (FIRST) {
            float2 o; o.x = dx; o.y = dy;
            S[gw] = o;
        } else {
            float2 s = S[gw];
            s.x = s.x + fmaxf(dx - s.x * dx, 0.0f);
            s.y = s.y + fmaxf(dy - s.y * dy, 0.0f);
            S[gw] = s;
        }
    };

    // ===================== prologue (slot(j) = j mod 6) ====================
    loadAfn(Ab + (z0 - 2) * PLANE, z0 - 2 >= 0, 4);
    loadAfn(Ab + (z0 - 1) * PLANE, z0 - 1 >= 0, 5);
    loadAfn(Ab + (z0    ) * PLANE, true, 0);
    loadAfn(Ab + (z0 + 1) * PLANE, true, 1);
    loadAfn(Ab + (z0 + 2) * PLANE, true, 2);
    loadAfn(Ab + (z0 + 3) * PLANE, true, 3);
    __syncthreads();

    compute_e(0, 5, 4, 0, z0 - 1 >= 0, false, EbB);          // e(z0-1)
    compute_e(1, 0, 5, 1, true, true, EbB + z0 * PLANE);     // e(z0)
    __syncthreads();

    compute_rx(0, 5);                       // rx(z0-1)
    compute_rx(1, 0);                       // rx(z0)
    capA = capture(0);                      // A(z0)
    capB = capture(1);                      // A(z0+1)
    __syncthreads();

    compute_e(0, 1, 0, 2, true, true, EbB + (z0 + 1) * PLANE);
    compute_e(1, 2, 1, 3, true, true, EbB + (z0 + 2) * PLANE);
    loadAfn(Ab + (z0 + 4) * PLANE, true, 4);
    loadAfn(Ab + (z0 + 5) * PLANE, true, 5);
    __syncthreads();

    compute_rx(0, 1);
    compute_rx(1, 2);
    __syncthreads();

    // ===================== main loop: 23 bodies, 2 planes each =============
    const float* pA = Ab  + (z0 + 6) * PLANE;  // loads planes w+4, w+5
    float* pE       = EbB + (z0 + 3) * PLANE;  // stores e(w+1), e(w+2)
    float* pS       = SbB + (z0    ) * PLANE;  // outputs w-2, w-1
    int w = z0 + 2;

    auto body = [&](int c1, int m1, int p1, int c2, int m2, int p2,
                    int L1, int L2, int r1, int r2s,
                    int a0, int a1, int a2, int b0s, int b1s, int b2s,
                    int cs0, int cs1)
    {
        compute_e(0, c1, m1, p1, true,         true,          pE);
        compute_e(1, c2, m2, p2, (w + 2) < DD, (w + 2) < z1,  pE + PLANE);
        loadAfn(pA,         (w + 4) < DD, L1);
        loadAfn(pA + PLANE, (w + 5) < DD, L2);
        __syncthreads();
        compute_rx(0, r1);
        compute_rx(1, r2s);
        do_output(a0,  a1,  a2,  pS,         capA);
        do_output(b0s, b1s, b2s, pS + PLANE, capB);
        capA = capture(cs0);
        capB = capture(cs1);
        __syncthreads();
        pA += 2 * PLANE; pE += 2 * PLANE; pS += 2 * PLANE;
        w += 2;
    };

    // phase w%6==2 / 4 / 0 (slots compile-time)
    #pragma unroll 1
    for (int m = 0; m < 7; m++) {
        body(3,2,4, 4,3,5, 0,1, 3,4, 5,0,1, 0,1,2, 2,3);
        body(5,4,0, 0,5,1, 2,3, 5,0, 1,2,3, 2,3,4, 4,5);
        body(1,0,2, 2,1,3, 4,5, 1,2, 3,4,5, 4,5,0, 0,1);
    }
    body(3,2,4, 4,3,5, 0,1, 3,4, 5,0,1, 0,1,2, 2,3);   // w = z0+44
    body(5,4,0, 0,5,1, 2,3, 5,0, 1,2,3, 2,3,4, 4,5);   // w = z0+46

    // epilogue: outputs z0+46 (slots 3,4,5) and z0+47 (slots 4,5,0)
    do_output(3, 4, 5, pS,         capA);
    do_output(4, 5, 0, pS + PLANE, capB);
}

extern "C" void kernel_launch(void* const* d_in, const int* in_sizes, int n_in,
                              void* d_out, int out_size) {
    const float* img = (const float*)d_in[0];
    float* skel = (float*)d_out;

    float *b0 = nullptr, *b1 = nullptr;
    cudaGetSymbolAddress((void**)&b0, g_buf0);
    cudaGetSymbolAddress((void**)&b1, g_buf1);

    cudaFuncSetAttribute((const void*)fused_step<1>,
                         cudaFuncAttributeMaxDynamicSharedMemorySize, SM_BYTES);
    cudaFuncSetAttribute((const void*)fused_step<0>,
                         cudaFuncAttributeMaxDynamicSharedMemorySize, SM_BYTES);

    dim3 grid(WW / 32, HH / 32, NCH * B);   // 6 x 6 x 8 = 288 blocks
    dim3 blk(NTHR, 1, 1);                   // 512 threads

    fused_step<1><<<grid, blk, SM_BYTES>>>(img, b0, skel);
    const float* src = b0;
    for (int kk = 1; kk <= 40; kk++) {
        float* dst = (kk & 1) ? b1 : b0;
        fused_step<0><<<grid, blk, SM_BYTES>>>(src, dst, skel);
        src = dst;
    }
}

// round 13
// speedup vs baseline: 2.5258x; 1.5548x over previous
#include <cuda_runtime.h>
#include <math_constants.h>

// Shapes: img (B=2, C=1, D=192, H=192, W=192) float32.
static constexpr int B   = 2;
static constexpr int DD  = 192;
static constexpr int HH  = 192;
static constexpr int WW  = 192;
static constexpr int PLANE = HH * WW;        // 36864
static constexpr int VOL   = DD * PLANE;     // 7077888
static constexpr int NTOT  = B * VOL;        // 14155776
static constexpr int WWW   = WW / 2;         // 96 gmem float2 words/row

static constexpr int NTHR = 512;
static constexpr int ZCHUNK = 48;            // z0 % 6 == 0
static constexpr int NCH    = DD / ZCHUNK;   // 4

// float2-word smem geometry
static constexpr int AWW = 18;               // A: 36 rows x 18 words (halo 2)
static constexpr int APW = 36 * AWW;         // 648
static constexpr int EWW = 18;               // e: 34 rows x 18 words (col c -> float idx c+1)
static constexpr int EPW = 34 * EWW;         // 612
static constexpr int RWW = 16;               // rx: 34 rows x 16 words
static constexpr int RPW = 34 * RWW;         // 544

static constexpr int SM_BYTES = (6 * APW + 6 * RPW + 2 * EPW) * 8;  // 67008

// Ping-pong erosion buffers (scratch: __device__ globals, no allocation).
__device__ float g_buf0[NTOT];
__device__ float g_buf1[NTOT];

// One fused soft-skeletonize step:
//   Eout = soft_erode(A)                 (7-pt cross min, +inf pad)
//   d    = dilate3x3x3(Eout)             (-inf pad)
//   delta = relu(A - d)
//   skel  = FIRST ? delta : skel + relu(delta - skel*delta)
// float2 datapath; 2 planes per iteration, 1 sync per plane; A-plane LDGs
// prefetched one body ahead into registers so barriers never wait on DRAM.
template <int FIRST>
__global__ __launch_bounds__(NTHR, 2)
void fused_step(const float* __restrict__ A,
                float* __restrict__ Eout,
                float* __restrict__ skel)
{
    extern __shared__ float2 sm2[];
    float2* As2 = sm2;                        // 6 planes, slot = j%6
    float2* rx2 = sm2 + 6 * APW;              // 6 planes, slot = j%6
    float2* eb2 = sm2 + 6 * APW + 6 * RPW;    // 2 scratch erode planes

    const int tid = threadIdx.x;
    const int x0  = blockIdx.x * 32;
    const int y0  = blockIdx.y * 32;
    const int bz  = blockIdx.z;
    const int bb  = bz >> 2;                  // NCH == 4
    const int z0  = (bz & 3) * ZCHUNK;        // z0 % 6 == 0
    const int z1  = z0 + ZCHUNK;

    const float* __restrict__ Ab = A    + bb * VOL;
    float* __restrict__ EbB      = Eout + bb * VOL;
    float* __restrict__ SbB      = skel + bb * VOL;

    const float PINF = CUDART_INF_F;
    const float NINF = -CUDART_INF_F;

    // ================= z-invariant per-thread precomputation ==============
    const int r = tid >> 4;                   // 0..31
    const int k = tid & 15;

    // e main pair: e row r, pair cols (2k+1, 2k+2); A word base row r+1
    const int  bA   = (r + 1) * AWW + k;
    const int  eStM = r * EWW + k + 1;
    const bool valE = ((unsigned)(y0 + r - 1) < (unsigned)HH);
    const bool stM  = (r >= 1);               // rows 1..31 store E
    const int  gEM  = (y0 + r - 1) * WWW + (x0 >> 1) + k;

    // e second pair (tid<32): rows 32,33 -> derived by +32*stride offsets
    const bool act2e = tid < 32;
    const bool stM2  = tid < 16;              // r2 == 32
    const bool valE2 = (tid < 16) || (y0 <= 159);

    // e edge scalars (tid in [64,132)): cols 0 and 33, rows 0..33
    const bool actEd = (tid >= 64) && (tid < 132);
    int aE = 0, eStE = 0; bool valEd = false;
    {
        int j   = tid - 64;
        int col = (j & 1) ? 33 : 0;
        int row = j >> 1;
        aE   = (row + 1) * 36 + (col + 1);    // A float idx
        eStE = row * 36 + (col + 1);          // e float idx
        int gx = x0 + col - 1;
        int gy = y0 + row - 1;
        valEd = actEd && ((unsigned)gx < (unsigned)WW) &&
                         ((unsigned)gy < (unsigned)HH);
    }

    // rx: main word at row r; second rows via +32*EWW
    const int rbM = r * EWW + k;

    // out / capture
    const int gw  = (y0 + r) * WWW + (x0 >> 1) + k;
    const int cAw = (r + 2) * AWW + k + 1;

    // loadA: 648 words = 512 + 136
    const bool actL1 = tid < (APW - NTHR);
    int la0g, la1g; bool la0v, la1v;
    {
        int row0 = tid / AWW, c0 = tid - row0 * AWW;
        int gy = y0 + row0 - 2, gx = x0 + 2 * c0 - 2;
        la0v = ((unsigned)gy < (unsigned)HH) && ((unsigned)gx < (unsigned)WW);
        la0g = la0v ? gy * WWW + (gx >> 1) : 0;
        int wi = tid + NTHR;
        int row1 = wi / AWW, c1 = wi - row1 * AWW;
        gy = y0 + row1 - 2; gx = x0 + 2 * c1 - 2;
        la1v = actL1 && ((unsigned)gy < (unsigned)HH) && ((unsigned)gx < (unsigned)WW);
        la1g = la1v ? gy * WWW + (gx >> 1) : 0;
    }

    float2 capA, capB;
    float2 pf0a, pf0b, pf1a, pf1b;   // prefetched A planes (regs)

    const float2 PINF2 = make_float2(CUDART_INF_F, CUDART_INF_F);

    // ========================= helpers ====================================

    // direct load (prologue only)
    auto loadAfn = [&](const float* src, bool zv, int slot) {
        float2* s = As2 + slot * APW;
        const float2* g = (const float2*)src;
        float2 v0 = (zv && la0v) ? __ldg(g + la0g) : PINF2;
        s[tid] = v0;
        if (actL1) {
            float2 v1 = (zv && la1v) ? __ldg(g + la1g) : PINF2;
            s[tid + NTHR] = v1;
        }
    };

    // register prefetch of two planes
    auto ldPrefetch = [&](const float* srcA, const float* srcB,
                          bool zvA, bool zvB) {
        const float2* g0 = (const float2*)srcA;
        const float2* g1 = (const float2*)srcB;
        pf0a = (zvA && la0v) ? __ldg(g0 + la0g) : PINF2;
        pf1a = (zvB && la0v) ? __ldg(g1 + la0g) : PINF2;
        if (actL1) {
            pf0b = (zvA && la1v) ? __ldg(g0 + la1g) : PINF2;
            pf1b = (zvB && la1v) ? __ldg(g1 + la1g) : PINF2;
        }
    };

    auto stsPrefetch = [&](int slotA, int slotB) {
        As2[slotA * APW + tid] = pf0a;
        As2[slotB * APW + tid] = pf1a;
        if (actL1) {
            As2[slotA * APW + tid + NTHR] = pf0b;
            As2[slotB * APW + tid + NTHR] = pf1b;
        }
    };

    auto compute_e = [&](int ep, int sC, int sM, int sP, bool jv,
                         bool st, float* pE) {
        float2* E = eb2 + ep * EPW;
        const float2* C = As2 + sC * APW;
        const float2* M = As2 + sM * APW;
        const float2* P = As2 + sP * APW;
        {   // main pair
            float2 w0 = C[bA], w1 = C[bA + 1], w2 = C[bA + 2];
            float2 up = C[bA + 1 - AWW], dn = C[bA + 1 + AWW];
            float2 zm = M[bA + 1], zp = P[bA + 1];
            float e0 = fminf(fminf(w1.x, fminf(up.x, dn.x)), fminf(zm.x, zp.x));
            e0 = fminf(e0, fminf(w0.y, w1.y));
            float e1 = fminf(fminf(w1.y, fminf(up.y, dn.y)), fminf(zm.y, zp.y));
            e1 = fminf(e1, fminf(w1.x, w2.x));
            bool v = jv && valE;
            float2 o; o.x = v ? e0 : NINF; o.y = v ? e1 : NINF;
            E[eStM] = o;
            if (st && stM) ((float2*)pE)[gEM] = o;
        }
        if (act2e) {  // rows 32,33 (offsets derived from main: +32*stride)
            const int bA2  = bA + 32 * AWW;
            const int eSt2 = eStM + 32 * EWW;
            float2 w0 = C[bA2], w1 = C[bA2 + 1], w2 = C[bA2 + 2];
            float2 up = C[bA2 + 1 - AWW], dn = C[bA2 + 1 + AWW];
            float2 zm = M[bA2 + 1], zp = P[bA2 + 1];
            float e0 = fminf(fminf(w1.x, fminf(up.x, dn.x)), fminf(zm.x, zp.x));
            e0 = fminf(e0, fminf(w0.y, w1.y));
            float e1 = fminf(fminf(w1.y, fminf(up.y, dn.y)), fminf(zm.y, zp.y));
            e1 = fminf(e1, fminf(w1.x, w2.x));
            bool v = jv && valE2;
            float2 o; o.x = v ? e0 : NINF; o.y = v ? e1 : NINF;
            E[eSt2] = o;
            if (st && stM2) ((float2*)pE)[gEM + 32 * WWW] = o;
        }
        if (actEd) {  // scalar edge cols
            const float* Cf = (const float*)C;
            float m = fminf(Cf[aE], fminf(Cf[aE - 1], Cf[aE + 1]));
            m = fminf(m, fminf(Cf[aE - 36], Cf[aE + 36]));
            m = fminf(m, fminf(((const float*)M)[aE], ((const float*)P)[aE]));
            ((float*)E)[eStE] = (jv && valEd) ? m : NINF;
        }
    };

    auto compute_rx = [&](int ep, int slot) {
        const float2* E = eb2 + ep * EPW;
        float2* R = rx2 + slot * RPW;
        {
            float2 w0 = E[rbM], w1 = E[rbM + 1], w2 = E[rbM + 2];
            float2 o;
            float c = fmaxf(w1.x, w1.y);
            o.x = fmaxf(w0.y, c);
            o.y = fmaxf(w2.x, c);
            R[tid] = o;
        }
        if (act2e) {
            const int rb2 = rbM + 32 * EWW;
            float2 w0 = E[rb2], w1 = E[rb2 + 1], w2 = E[rb2 + 2];
            float2 o;
            float c = fmaxf(w1.x, w1.y);
            o.x = fmaxf(w0.y, c);
            o.y = fmaxf(w2.x, c);
            R[NTHR + tid] = o;
        }
    };

    auto capture = [&](int slot) { return As2[slot * APW + cAw]; };

    auto do_output = [&](int s0, int s1, int s2, float* pS, float2 a,
                         float2 sPre) {
        const float2* R0 = rx2 + s0 * RPW;
        const float2* R1 = rx2 + s1 * RPW;
        const float2* R2 = rx2 + s2 * RPW;
        float2 m = R0[tid];
        float2 t;
        t = R0[tid + RWW];     m.x = fmaxf(m.x, t.x); m.y = fmaxf(m.y, t.y);
        t = R0[tid + 2*RWW];   m.x = fmaxf(m.x, t.x); m.y = fmaxf(m.y, t.y);
        t = R1[tid];           m.x = fmaxf(m.x, t.x); m.y = fmaxf(m.y, t.y);
        t = R1[tid + RWW];     m.x = fmaxf(m.x, t.x); m.y = fmaxf(m.y, t.y);
        t = R1[tid + 2*RWW];   m.x = fmaxf(m.x, t.x); m.y = fmaxf(m.y, t.y);
        t = R2[tid];           m.x = fmaxf(m.x, t.x); m.y = fmaxf(m.y, t.y);
        t = R2[tid + RWW];     m.x = fmaxf(m.x, t.x); m.y = fmaxf(m.y, t.y);
        t = R2[tid + 2*RWW];   m.x = fmaxf(m.x, t.x); m.y = fmaxf(m.y, t.y);
        float dx = fmaxf(a.x - m.x, 0.0f);
        float dy = fmaxf(a.y - m.y, 0.0f);
        float2* S = (float2*)pS;
        if (FIRST) {
            float2 o; o.x = dx; o.y = dy;
            S[gw] = o;
        } else {
            float2 s = sPre;
            s.x = s.x + fmaxf(dx - s.x * dx, 0.0f);
            s.y = s.y + fmaxf(dy - s.y * dy, 0.0f);
            S[gw] = s;
        }
    };

    // ===================== prologue (slot(j) = j mod 6) ====================
    loadAfn(Ab + (z0 - 2) * PLANE, z0 - 2 >= 0, 4);
    loadAfn(Ab + (z0 - 1) * PLANE, z0 - 1 >= 0, 5);
    loadAfn(Ab + (z0    ) * PLANE, true, 0);
    loadAfn(Ab + (z0 + 1) * PLANE, true, 1);
    loadAfn(Ab + (z0 + 2) * PLANE, true, 2);
    loadAfn(Ab + (z0 + 3) * PLANE, true, 3);
    __syncthreads();

    compute_e(0, 5, 4, 0, z0 - 1 >= 0, false, EbB);          // e(z0-1)
    compute_e(1, 0, 5, 1, true, true, EbB + z0 * PLANE);     // e(z0)
    __syncthreads();

    compute_rx(0, 5);                       // rx(z0-1)
    compute_rx(1, 0);                       // rx(z0)
    capA = capture(0);                      // A(z0)
    capB = capture(1);                      // A(z0+1)
    __syncthreads();

    compute_e(0, 1, 0, 2, true, true, EbB + (z0 + 1) * PLANE);
    compute_e(1, 2, 1, 3, true, true, EbB + (z0 + 2) * PLANE);
    loadAfn(Ab + (z0 + 4) * PLANE, true, 4);
    loadAfn(Ab + (z0 + 5) * PLANE, true, 5);
    __syncthreads();

    compute_rx(0, 1);
    compute_rx(1, 2);
    __syncthreads();

    // ===================== main loop: 25 bodies, 2 planes each =============
    const float* pA = Ab  + (z0 + 6) * PLANE;  // plane w+4
    float* pE       = EbB + (z0 + 3) * PLANE;  // stores e(w+1), e(w+2)
    float* pS       = SbB + (z0    ) * PLANE;  // outputs w-2, w-1
    int w = z0 + 2;

    // prime prefetch regs with planes z0+6, z0+7 (always < DD: z0 <= 144)
    ldPrefetch(pA, pA + PLANE, true, true);

    auto body = [&](int c1, int m1, int p1, int c2, int m2, int p2,
                    int L1, int L2, int r1, int r2s,
                    int a0, int a1, int a2, int b0s, int b1s, int b2s,
                    int cs0, int cs1)
    {
        stsPrefetch(L1, L2);                       // planes w+4, w+5
        ldPrefetch(pA + 2 * PLANE, pA + 3 * PLANE, // planes w+6, w+7
                   (w + 6) < DD, (w + 7) < DD);
        compute_e(0, c1, m1, p1, true,         true,          pE);
        compute_e(1, c2, m2, p2, (w + 2) < DD, (w + 2) < z1,  pE + PLANE);
        __syncthreads();
        float2 sp0 = PINF2, sp1 = PINF2;
        if (!FIRST) {                              // early skel loads
            sp0 = ((const float2*)pS)[gw];
            sp1 = ((const float2*)(pS + PLANE))[gw];
        }
        compute_rx(0, r1);
        compute_rx(1, r2s);
        do_output(a0,  a1,  a2,  pS,         capA, sp0);
        do_output(b0s, b1s, b2s, pS + PLANE, capB, sp1);
        capA = capture(cs0);
        capB = capture(cs1);
        __syncthreads();
        pA += 2 * PLANE; pE += 2 * PLANE; pS += 2 * PLANE;
        w += 2;
    };

    // phase w%6==2 / 4 / 0 (slots compile-time)
    #pragma unroll 1
    for (int m = 0; m < 7; m++) {
        body(3,2,4, 4,3,5, 0,1, 3,4, 5,0,1, 0,1,2, 2,3);
        body(5,4,0, 0,5,1, 2,3, 5,0, 1,2,3, 2,3,4, 4,5);
        body(1,0,2, 2,1,3, 4,5, 1,2, 3,4,5, 4,5,0, 0,1);
    }
    body(3,2,4, 4,3,5, 0,1, 3,4, 5,0,1, 0,1,2, 2,3);   // w = z0+44
    body(5,4,0, 0,5,1, 2,3, 5,0, 1,2,3, 2,3,4, 4,5);   // w = z0+46

    // epilogue: outputs z0+46 (slots 3,4,5) and z0+47 (slots 4,5,0)
    float2 es0 = PINF2, es1 = PINF2;
    if (!FIRST) {
        es0 = ((const float2*)pS)[gw];
        es1 = ((const float2*)(pS + PLANE))[gw];
    }
    do_output(3, 4, 5, pS,         capA, es0);
    do_output(4, 5, 0, pS + PLANE, capB, es1);
}

extern "C" void kernel_launch(void* const* d_in, const int* in_sizes, int n_in,
                              void* d_out, int out_size) {
    const float* img = (const float*)d_in[0];
    float* skel = (float*)d_out;

    float *b0 = nullptr, *b1 = nullptr;
    cudaGetSymbolAddress((void**)&b0, g_buf0);
    cudaGetSymbolAddress((void**)&b1, g_buf1);

    cudaFuncSetAttribute((const void*)fused_step<1>,
                         cudaFuncAttributeMaxDynamicSharedMemorySize, SM_BYTES);
    cudaFuncSetAttribute((const void*)fused_step<0>,
                         cudaFuncAttributeMaxDynamicSharedMemorySize, SM_BYTES);

    dim3 grid(WW / 32, HH / 32, NCH * B);   // 6 x 6 x 8 = 288 blocks
    dim3 blk(NTHR, 1, 1);                   // 512 threads

    fused_step<1><<<grid, blk, SM_BYTES>>>(img, b0, skel);
    const float* src = b0;
    for (int kk = 1; kk <= 40; kk++) {
        float* dst = (kk & 1) ? b1 : b0;
        fused_step<0><<<grid, blk, SM_BYTES>>>(src, dst, skel);
        src = dst;
    }
}